// round 1
// baseline (speedup 1.0000x reference)
#include <cuda_runtime.h>
#include <cuda_bf16.h>

// Problem: X[16,1024,2], Y[16,1024,8] -> out = [grid(4096,2), Y_grid(16,4096,9)]
// Separable Gaussian: K[(i,j),n] = A[i,n]*B[j,n],
//   A[i,n] = exp(-2*(lin_i - x0_n)^2), B[j,n] = exp(-2*(lin_j - x1_n)^2)

#define NB   16
#define NN   1024
#define NAX  64
#define NC   9          // density + 8 feats
#define STEP (6.0f / 63.0f)
#define GRID_ELEMS (4096 * 2)

// Scratch (allocation-free rule: __device__ globals)
__device__ float g_A[NB * NAX * NN];   // [b][i][n]
__device__ float g_B[NB * NAX * NN];   // [b][j][n]

// ---- packed f32x2 helpers ----
#define PACK2(out, lo, hi) \
    asm("mov.b64 %0, {%1, %2};" : "=l"(out) : "f"(lo), "f"(hi))
#define UNPACK2(lo, hi, in) \
    asm("mov.b64 {%0, %1}, %2;" : "=f"(lo), "=f"(hi) : "l"(in))
#define FMA2(d, a, b, c) \
    asm("fma.rn.f32x2 %0, %1, %2, %3;" : "=l"(d) : "l"(a), "l"(b), "l"(c))

// Kernel 1: precompute A, B; write grid coords to d_out[0..8191]
__global__ __launch_bounds__(256)
void rkhs_precomp_kernel(const float* __restrict__ X, float* __restrict__ out)
{
    int tid = blockIdx.x * blockDim.x + threadIdx.x;

    if (tid < 4096) {
        int i = tid >> 6, j = tid & 63;
        out[tid * 2 + 0] = -3.0f + (float)i * STEP;
        out[tid * 2 + 1] = -3.0f + (float)j * STEP;
    }

    const int TOT = NB * NAX * NN;   // 1M
    int stride = gridDim.x * blockDim.x;
    for (int idx = tid; idx < TOT; idx += stride) {
        int b = idx >> 16;           // / (64*1024)
        int r = idx & 65535;
        int i = r >> 10;
        int n = r & 1023;
        float li = -3.0f + (float)i * STEP;
        float2 x = ((const float2*)X)[b * NN + n];   // (x0, x1)
        float t0 = li - x.x;
        float t1 = li - x.y;
        g_A[idx] = __expf(-2.0f * t0 * t0);
        g_B[idx] = __expf(-2.0f * t1 * t1);
    }
}

// Kernel 2: out[b,i,j,c] = sum_n A[i,n]*B[j,n]*Yb[n,c]; then feats /= (density+eps)
// Grid: 128 CTAs = 16 b * 8 j-tiles. 256 threads: i = t&63, jg = t>>6 (owns 2 j).
#define CN 128   // n-chunk

__global__ __launch_bounds__(256)
void rkhs_main_kernel(const float* __restrict__ Y, float* __restrict__ out)
{
    const int b  = blockIdx.x >> 3;
    const int jt = blockIdx.x & 7;

    __shared__ __align__(16) float  sA[NAX * (CN + 1)];   // stride 129: conflict-free
    __shared__ __align__(16) float2 sBt[CN * 4];          // [nn][jg] = (B_j0, B_j1)
    __shared__ __align__(16) float  sY[CN * 10];          // [nn] = [1, Y0..Y7, 0]

    const int t  = threadIdx.x;
    const int i  = t & 63;
    const int jg = t >> 6;                                 // 0..3

    unsigned long long acc0[5], acc1[5];
#pragma unroll
    for (int k = 0; k < 5; ++k) { acc0[k] = 0ULL; acc1[k] = 0ULL; }

    const float* Ab = g_A + b * (NAX * NN);
    const float* Bb = g_B + b * (NAX * NN) + (jt * 8) * NN;
    const float* Yb = Y + b * (NN * 8);

    for (int n0 = 0; n0 < NN; n0 += CN) {
        // stage A chunk: [64][128], coalesced LDG, padded STS
        for (int idx = t; idx < NAX * CN; idx += 256) {
            int ii = idx >> 7, nn = idx & (CN - 1);
            sA[ii * (CN + 1) + nn] = Ab[ii * NN + n0 + nn];
        }
        // stage B chunk as interleaved pairs: ((float*)sBt)[nn*8 + jl]
        for (int idx = t; idx < 8 * CN; idx += 256) {
            int nn = idx & (CN - 1), jl = idx >> 7;
            ((float*)sBt)[nn * 8 + jl] = Bb[jl * NN + n0 + nn];
        }
        // stage Yb rows: [1, Y0..Y7, 0]
        for (int idx = t; idx < 10 * CN; idx += 256) {
            int nn = idx & (CN - 1), c = idx >> 7;        // c 0..9
            float v;
            if (c == 0)      v = 1.0f;
            else if (c == 9) v = 0.0f;
            else             v = Yb[(n0 + nn) * 8 + (c - 1)];
            sY[nn * 10 + c] = v;
        }
        __syncthreads();

        const float* aRow = sA + i * (CN + 1);
#pragma unroll 4
        for (int nn = 0; nn < CN; ++nn) {
            float a = aRow[nn];                            // conflict-free LDS
            float2 bp = sBt[nn * 4 + jg];                  // warp broadcast
            float ab0 = a * bp.x;
            float ab1 = a * bp.y;
            unsigned long long p0, p1;
            PACK2(p0, ab0, ab0);
            PACK2(p1, ab1, ab1);
            const unsigned long long* yp =
                (const unsigned long long*)(sY + nn * 10); // broadcast, 8B aligned
#pragma unroll
            for (int k = 0; k < 5; ++k) {
                unsigned long long y = yp[k];
                FMA2(acc0[k], p0, y, acc0[k]);
                FMA2(acc1[k], p1, y, acc1[k]);
            }
        }
        __syncthreads();
    }

    // Epilogue: unpack, divide feats by (density + eps), write
    float v0[10], v1[10];
#pragma unroll
    for (int k = 0; k < 5; ++k) {
        UNPACK2(v0[2 * k], v0[2 * k + 1], acc0[k]);
        UNPACK2(v1[2 * k], v1[2 * k + 1], acc1[k]);
    }

    const int j0 = jt * 8 + jg * 2;
    float r0 = 1.0f / (v0[0] + 1e-6f);
    float r1 = 1.0f / (v1[0] + 1e-6f);

    float* o = out + GRID_ELEMS + (size_t)((b * 4096 + i * 64 + j0)) * NC;
    o[0] = v0[0];
#pragma unroll
    for (int c = 1; c < 9; ++c) o[c] = v0[c] * r0;
    float* o2 = o + NC;
    o2[0] = v1[0];
#pragma unroll
    for (int c = 1; c < 9; ++c) o2[c] = v1[c] * r1;
}

extern "C" void kernel_launch(void* const* d_in, const int* in_sizes, int n_in,
                              void* d_out, int out_size)
{
    const float* X = (const float*)d_in[0];   // [16,1024,2]
    const float* Y = (const float*)d_in[1];   // [16,1024,8]
    float* out = (float*)d_out;               // grid(8192) ++ Y_grid(16*4096*9)

    rkhs_precomp_kernel<<<512, 256>>>(X, out);
    rkhs_main_kernel<<<128, 256>>>(Y, out);
}

// round 2
// speedup vs baseline: 1.3313x; 1.3313x over previous
#include <cuda_runtime.h>
#include <cuda_bf16.h>

// X[16,1024,2], Y[16,1024,8] -> out = [grid(4096,2), Y_grid(16,4096,9)]
// Separable: K[(i,j),n] = A[i,n]*B[j,n]
#define NB   16
#define NN   1024
#define NAX  64
#define NC   9
#define STEP (6.0f / 63.0f)
#define GRID_ELEMS (4096 * 2)
#define NSPLIT 4
#define NPER   (NN / NSPLIT)    // 256
#define CN     128
#define OUTIJ  (NB * 4096)      // 65536 (b,i,j) rows

__device__ float g_A[NB * NAX * NN];                  // [b][i][n]
__device__ float g_B[NB * NAX * NN];                  // [b][j][n]
__device__ float g_part[NSPLIT * OUTIJ * 10];         // partial sums (10 = 9 + pad)

#define UNPACK2(lo, hi, in) \
    asm("mov.b64 {%0, %1}, %2;" : "=f"(lo), "=f"(hi) : "l"(in))
#define PACK2(out, lo, hi) \
    asm("mov.b64 %0, {%1, %2};" : "=l"(out) : "f"(lo), "f"(hi))
#define FMA2(d, a, b, c) \
    asm("fma.rn.f32x2 %0, %1, %2, %3;" : "=l"(d) : "l"(a), "l"(b), "l"(c))

// ---------- Kernel 1: precompute A, B + write grid coords ----------
__global__ __launch_bounds__(256)
void rkhs_precomp_kernel(const float* __restrict__ X, float* __restrict__ out)
{
    int tid = blockIdx.x * blockDim.x + threadIdx.x;

    if (tid < 4096) {
        int i = tid >> 6, j = tid & 63;
        out[tid * 2 + 0] = -3.0f + (float)i * STEP;
        out[tid * 2 + 1] = -3.0f + (float)j * STEP;
    }

    const int TOT = NB * NAX * NN;
    int stride = gridDim.x * blockDim.x;
    for (int idx = tid; idx < TOT; idx += stride) {
        int b = idx >> 16;
        int r = idx & 65535;
        int i = r >> 10;
        int n = r & 1023;
        float li = -3.0f + (float)i * STEP;
        float2 x = ((const float2*)X)[b * NN + n];
        float t0 = li - x.x;
        float t1 = li - x.y;
        g_A[idx] = __expf(-2.0f * t0 * t0);
        g_B[idx] = __expf(-2.0f * t1 * t1);
    }
}

// ---------- Kernel 2: partial contraction over an n-slice ----------
// Grid: 512 = b(16) * jt(8) * ns(4). Threads 256: i = t&63, jg = t>>6 (2 j's).
__global__ __launch_bounds__(256)
void rkhs_main_kernel(const float* __restrict__ Y)
{
    const int ns = blockIdx.x & 3;
    const int jt = (blockIdx.x >> 2) & 7;
    const int b  = blockIdx.x >> 5;

    __shared__ __align__(16) float  sA[NAX * (CN + 1)];  // stride 129
    __shared__ __align__(16) float2 sBt[CN * 4];         // [nn][jg]
    __shared__ __align__(16) float  sY[CN * 12];         // [nn] = [1,Y0..Y7,0,0,0]

    const int t  = threadIdx.x;
    const int i  = t & 63;
    const int jg = t >> 6;

    unsigned long long acc0[5], acc1[5];
#pragma unroll
    for (int k = 0; k < 5; ++k) { acc0[k] = 0ULL; acc1[k] = 0ULL; }

    const float* Ab = g_A + b * (NAX * NN);
    const float* Bb = g_B + b * (NAX * NN) + (jt * 8) * NN;
    const float* Yb = Y + b * (NN * 8);

    const int nbase = ns * NPER;
    for (int n0 = nbase; n0 < nbase + NPER; n0 += CN) {
        for (int idx = t; idx < NAX * CN; idx += 256) {
            int ii = idx >> 7, nn = idx & (CN - 1);
            sA[ii * (CN + 1) + nn] = Ab[ii * NN + n0 + nn];
        }
        for (int idx = t; idx < 8 * CN; idx += 256) {
            int nn = idx & (CN - 1), jl = idx >> 7;
            ((float*)sBt)[nn * 8 + jl] = Bb[jl * NN + n0 + nn];
        }
        for (int idx = t; idx < 12 * CN; idx += 256) {
            int nn = idx / 12, c = idx - nn * 12;
            float v;
            if (c == 0)     v = 1.0f;
            else if (c < 9) v = Yb[(n0 + nn) * 8 + (c - 1)];
            else            v = 0.0f;
            sY[nn * 12 + c] = v;
        }
        __syncthreads();

        const float* aRow = sA + i * (CN + 1);
#pragma unroll 4
        for (int nn = 0; nn < CN; ++nn) {
            float a = aRow[nn];                    // conflict-free
            float2 bp = sBt[nn * 4 + jg];          // warp broadcast
            float ab0 = a * bp.x;
            float ab1 = a * bp.y;
            unsigned long long p0, p1;
            PACK2(p0, ab0, ab0);
            PACK2(p1, ab1, ab1);
            const char* row = (const char*)(sY + nn * 12);   // 16B aligned
            ulonglong2 ya = *(const ulonglong2*)row;         // pairs 0,1
            ulonglong2 yb2 = *(const ulonglong2*)(row + 16); // pairs 2,3
            unsigned long long yc = *(const unsigned long long*)(row + 32);
            FMA2(acc0[0], p0, ya.x,  acc0[0]);
            FMA2(acc1[0], p1, ya.x,  acc1[0]);
            FMA2(acc0[1], p0, ya.y,  acc0[1]);
            FMA2(acc1[1], p1, ya.y,  acc1[1]);
            FMA2(acc0[2], p0, yb2.x, acc0[2]);
            FMA2(acc1[2], p1, yb2.x, acc1[2]);
            FMA2(acc0[3], p0, yb2.y, acc0[3]);
            FMA2(acc1[3], p1, yb2.y, acc1[3]);
            FMA2(acc0[4], p0, yc,    acc0[4]);
            FMA2(acc1[4], p1, yc,    acc1[4]);
        }
        __syncthreads();
    }

    // Write raw partials: row stride 10 floats, ST.64 x5 per j
    const int j0 = jt * 8 + jg * 2;
    const int ij = b * 4096 + i * 64 + j0;
    unsigned long long* p = (unsigned long long*)(g_part + ((size_t)ns * OUTIJ + ij) * 10);
#pragma unroll
    for (int k = 0; k < 5; ++k) p[k] = acc0[k];
    unsigned long long* p2 = (unsigned long long*)(g_part + ((size_t)ns * OUTIJ + ij + 1) * 10);
#pragma unroll
    for (int k = 0; k < 5; ++k) p2[k] = acc1[k];
}

// ---------- Kernel 3: reduce partials, normalize, write ----------
__global__ __launch_bounds__(256)
void rkhs_reduce_kernel(float* __restrict__ out)
{
    int tid = blockIdx.x * blockDim.x + threadIdx.x;   // 0..65535 (b,ij)
    if (tid >= OUTIJ) return;

    float s[10];
#pragma unroll
    for (int c = 0; c < 10; ++c) s[c] = 0.0f;
#pragma unroll
    for (int ns = 0; ns < NSPLIT; ++ns) {
        const float2* p = (const float2*)(g_part + ((size_t)ns * OUTIJ + tid) * 10);
#pragma unroll
        for (int k = 0; k < 5; ++k) {
            float2 v = p[k];
            s[2 * k]     += v.x;
            s[2 * k + 1] += v.y;
        }
    }
    float r = 1.0f / (s[0] + 1e-6f);
    float* o = out + GRID_ELEMS + (size_t)tid * NC;
    o[0] = s[0];
#pragma unroll
    for (int c = 1; c < 9; ++c) o[c] = s[c] * r;
}

extern "C" void kernel_launch(void* const* d_in, const int* in_sizes, int n_in,
                              void* d_out, int out_size)
{
    const float* X = (const float*)d_in[0];
    const float* Y = (const float*)d_in[1];
    float* out = (float*)d_out;

    rkhs_precomp_kernel<<<512, 256>>>(X, out);
    rkhs_main_kernel<<<512, 256>>>(Y);
    rkhs_reduce_kernel<<<256, 256>>>(out);
}